// round 12
// baseline (speedup 1.0000x reference)
#include <cuda_runtime.h>
#include <cuda_fp16.h>
#include <cstdint>

#define HWX   3136
#define WW    56
#define CTOT  256
#define NIMG  64
#define NPIX  (NIMG * HWX)          // 200704
#define NTILE 50176                 // 64 img * 28*28 winograd tiles

// Intermediate y, NHWC fp32: [img*hw][256]
__device__ float g_y[(size_t)NPIX * CTOT];
// Winograd-transformed input V[pos 16][tile][ic 256], fp16
__device__ __half g_V[(size_t)16 * NTILE * 256];
// Winograd-transformed weights, fp16
__device__ __half g_UA[16 * 64 * 64];      // [p][oc][ic]
__device__ __half g_UB[16 * 192 * 192];    // [p][oc][ic]

__device__ __forceinline__ uint32_t smem_u32(const void* p) {
    uint32_t a;
    asm("{ .reg .u64 t; cvta.to.shared.u64 t, %1; cvt.u32.u64 %0, t; }" : "=r"(a) : "l"(p));
    return a;
}

// ---------------------------------------------------------------------------
// Stage 1: temporal DW conv, NCHW fp32 -> NHWC fp32, smem transpose.
// ---------------------------------------------------------------------------
__global__ __launch_bounds__(256) void temporal_nhwc_kernel(
    const float* __restrict__ x,
    const float* __restrict__ w11, const float* __restrict__ w13,
    const float* __restrict__ w15, const float* __restrict__ w17,
    const float* __restrict__ w21, const float* __restrict__ w23,
    const float* __restrict__ w25, const float* __restrict__ w27)
{
    __shared__ float s[32][33];
    const int tx = threadIdx.x, ty = threadIdx.y;
    const int n = blockIdx.z, c0 = blockIdx.y * 32, hw0 = blockIdx.x * 32;

    float v[4][8], o[4][8];
#pragma unroll
    for (int j = 0; j < 4; j++) {
        int c = c0 + ty * 4 + j;
        const float* xb = x + ((size_t)(n * 8) * CTOT + c) * HWX + hw0 + tx;
#pragma unroll
        for (int t = 0; t < 8; t++) v[j][t] = xb[(size_t)t * CTOT * HWX];
    }
#pragma unroll
    for (int j = 0; j < 4; j++) {
        int c = c0 + ty * 4 + j;
        int k, cg; const float* wp;
        if      (c < 16)  { k = 1; wp = w11; cg = c;       }
        else if (c < 32)  { k = 3; wp = w13; cg = c - 16;  }
        else if (c < 48)  { k = 5; wp = w15; cg = c - 32;  }
        else if (c < 64)  { k = 7; wp = w17; cg = c - 48;  }
        else if (c < 112) { k = 1; wp = w21; cg = c - 64;  }
        else if (c < 160) { k = 3; wp = w23; cg = c - 112; }
        else if (c < 208) { k = 5; wp = w25; cg = c - 160; }
        else              { k = 7; wp = w27; cg = c - 208; }
        float wr[7];
#pragma unroll
        for (int q = 0; q < 7; q++) wr[q] = (q < k) ? __ldg(&wp[cg * k + q]) : 0.0f;
        int pad = (k - 1) >> 1;
#pragma unroll
        for (int t = 0; t < 8; t++) {
            float sum = 0.0f;
#pragma unroll
            for (int q = 0; q < 7; q++) {
                int tt = t + q - pad;
                if (q < k && tt >= 0 && tt < 8) sum += wr[q] * v[j][tt];
            }
            o[j][t] = sum;
        }
    }
#pragma unroll
    for (int t = 0; t < 8; t++) {
#pragma unroll
        for (int j = 0; j < 4; j++) s[tx][ty * 4 + j] = o[j][t];
        __syncthreads();
        float* yb = g_y + ((size_t)(n * 8 + t) * HWX + hw0) * CTOT + c0;
#pragma unroll
        for (int j = 0; j < 4; j++)
            yb[(size_t)(ty * 4 + j) * CTOT + tx] = s[ty * 4 + j][tx];
        __syncthreads();
    }
}

// ---------------------------------------------------------------------------
// Winograd input transform: g_y (NHWC fp32) -> V[p][tile][ic] fp16.
// ---------------------------------------------------------------------------
__global__ __launch_bounds__(256) void wino_v_kernel()
{
    const int tid  = threadIdx.x;
    const int tile = blockIdx.x * 2 + (tid >> 7);
    const int icp  = tid & 127;
    const int img  = tile / 784, rem = tile % 784;
    const int tr = rem / 28, tc = rem % 28;
    const int h0 = 2 * tr - 1, w0 = 2 * tc - 1;
    const float* yb = g_y + (size_t)img * HWX * CTOT + icp * 2;

    float ex[4][4], ey[4][4];
#pragma unroll
    for (int c = 0; c < 4; ++c) {
        float dx[4], dy[4];
#pragma unroll
        for (int r = 0; r < 4; ++r) {
            int h = h0 + r, w = w0 + c;
            float2 v = make_float2(0.0f, 0.0f);
            if ((unsigned)h < 56u && (unsigned)w < 56u)
                v = *(const float2*)(yb + (size_t)(h * WW + w) * CTOT);
            dx[r] = v.x; dy[r] = v.y;
        }
        ex[0][c] = dx[0] - dx[2];  ey[0][c] = dy[0] - dy[2];
        ex[1][c] = dx[1] + dx[2];  ey[1][c] = dy[1] + dy[2];
        ex[2][c] = dx[2] - dx[1];  ey[2][c] = dy[2] - dy[1];
        ex[3][c] = dx[1] - dx[3];  ey[3][c] = dy[1] - dy[3];
    }
#pragma unroll
    for (int i = 0; i < 4; ++i) {
        float vx[4], vy[4];
        vx[0] = ex[i][0] - ex[i][2];  vy[0] = ey[i][0] - ey[i][2];
        vx[1] = ex[i][1] + ex[i][2];  vy[1] = ey[i][1] + ey[i][2];
        vx[2] = ex[i][2] - ex[i][1];  vy[2] = ey[i][2] - ey[i][1];
        vx[3] = ex[i][1] - ex[i][3];  vy[3] = ey[i][1] - ey[i][3];
#pragma unroll
        for (int j = 0; j < 4; ++j) {
            *(__half2*)(g_V + ((size_t)(i * 4 + j) * NTILE + tile) * 256 + icp * 2)
                = __floats2half2_rn(vx[j], vy[j]);
        }
    }
}

// ---------------------------------------------------------------------------
// Winograd weight transform: U = G g G^T.
// ---------------------------------------------------------------------------
__global__ void wino_u_kernel(const float* __restrict__ w2d1,
                              const float* __restrict__ w2d2)
{
    int i = blockIdx.x * 256 + threadIdx.x;
    if (i >= 4096 + 36864) return;
    const float* src;
    __half* dst0; int rstride, rowoff;
    if (i < 4096) {
        int oc = i >> 6, ic = i & 63;
        src = w2d1 + (oc * 64 + ic) * 9;
        dst0 = g_UA; rstride = 64 * 64; rowoff = oc * 64 + ic;
    } else {
        int j = i - 4096;
        int oc = j / 192, ic = j % 192;
        src = w2d2 + (oc * 192 + ic) * 9;
        dst0 = g_UB; rstride = 192 * 192; rowoff = oc * 192 + ic;
    }
    float g[3][3];
#pragma unroll
    for (int a = 0; a < 3; ++a)
#pragma unroll
        for (int b = 0; b < 3; ++b) g[a][b] = src[a * 3 + b];
    float u[4][3];
#pragma unroll
    for (int b = 0; b < 3; ++b) {
        u[0][b] = g[0][b];
        u[1][b] = 0.5f * (g[0][b] + g[1][b] + g[2][b]);
        u[2][b] = 0.5f * (g[0][b] - g[1][b] + g[2][b]);
        u[3][b] = g[2][b];
    }
#pragma unroll
    for (int r = 0; r < 4; ++r) {
        float U0 = u[r][0];
        float U1 = 0.5f * (u[r][0] + u[r][1] + u[r][2]);
        float U2 = 0.5f * (u[r][0] - u[r][1] + u[r][2]);
        float U3 = u[r][2];
        dst0[(r * 4 + 0) * rstride + rowoff] = __float2half_rn(U0);
        dst0[(r * 4 + 1) * rstride + rowoff] = __float2half_rn(U1);
        dst0[(r * 4 + 2) * rstride + rowoff] = __float2half_rn(U2);
        dst0[(r * 4 + 3) * rstride + rowoff] = __float2half_rn(U3);
    }
}

// ---------------------------------------------------------------------------
// Winograd GEMM v3: compile-time-specialized position-level pipeline.
// All strides/counts constexpr; staging addressing = shifts only.
// CTA: 64 oc x 64 tiles, 8 warps (4 x 16 oc, 2 x 32 tiles). 2 buffers.
// ---------------------------------------------------------------------------
#define SMEM_BYTES 102400u       // 2 x 128 rows x 400 B (ICN=192 case)

#define LDSM_X4(r0, r1, r2, r3, addr) \
    asm volatile("ldmatrix.sync.aligned.m8n8.x4.shared.b16 {%0,%1,%2,%3}, [%4];" \
        : "=r"(r0), "=r"(r1), "=r"(r2), "=r"(r3) : "r"(addr))

template<bool ISA>
__device__ __forceinline__ void wino_body(float* __restrict__ out,
                                          const __half* __restrict__ smh_dummy)
{
    constexpr int ICN = ISA ? 64 : 192;
    constexpr uint32_t ST    = (uint32_t)(ICN * 2 + 16);   // 144 / 400 B per row
    constexpr uint32_t BOFF  = 64u * ST;
    constexpr uint32_t BUFSZ = 128u * ST;
    constexpr int CHT = ICN / 32;          // 16B chunks per thread: 2 / 6
    constexpr int NKS = ICN / 16;          // K-steps: 4 / 12
    constexpr size_t APS = (size_t)ICN * (ISA ? 64 : 192); // per-position A stride
    constexpr size_t BPS = (size_t)NTILE * 256;

    const uint32_t smb = smem_u32(smh_dummy);
    const int tid = threadIdx.x, wid = tid >> 5, lane = tid & 31;
    const int octile = blockIdx.x;
    const int n0 = blockIdx.y * 64;

    const __half* pa = ISA ? g_UA
                           : g_UB + (size_t)((octile - 1) * 64) * 192;
    const __half* pb = g_V + (size_t)n0 * 256 + (ISA ? 0 : 64);

    // shift-only staging addressing: 64 rows x 4 thread-groups of CHT chunks
    const int row = tid >> 2;
    const int kb0 = (tid & 3) * CHT;
    const uint32_t dA0 = smb + row * ST + kb0 * 16;
    const uint32_t dB0 = dA0 + BOFF;
    pa += (size_t)row * ICN + kb0 * 8;
    pb += (size_t)row * 256 + kb0 * 8;

    auto stage = [&](uint32_t buf) {
        const uint32_t bb = buf * BUFSZ;
#pragma unroll
        for (int j = 0; j < CHT; ++j)
            asm volatile("cp.async.cg.shared.global [%0], [%1], 16;"
                         :: "r"(dA0 + bb + j * 16), "l"(pa + j * 8));
#pragma unroll
        for (int j = 0; j < CHT; ++j)
            asm volatile("cp.async.cg.shared.global [%0], [%1], 16;"
                         :: "r"(dB0 + bb + j * 16), "l"(pb + j * 8));
        asm volatile("cp.async.commit_group;" ::: "memory");
        pa += APS; pb += BPS;
    };

    float Z[4][4][4];
#pragma unroll
    for (int a = 0; a < 4; ++a)
#pragma unroll
        for (int b = 0; b < 4; ++b)
#pragma unroll
            for (int c = 0; c < 4; ++c) Z[a][b][c] = 0.0f;

    const int wm = wid & 3, wn = wid >> 2;
    const int l15 = lane & 15;
    const int kh16 = (lane >> 4) * 16;
    const uint32_t aAo = (wm * 16 + l15) * ST + kh16;
    const uint32_t aBo = BOFF + (wn * 32 + l15) * ST + kh16;

    stage(0);

    for (int p = 0; p < 16; ++p) {
        if (p < 15) {
            stage((p + 1) & 1);
            asm volatile("cp.async.wait_group 1;" ::: "memory");
        } else {
            asm volatile("cp.async.wait_group 0;" ::: "memory");
        }
        __syncthreads();

        float M[4][4];
#pragma unroll
        for (int a = 0; a < 4; ++a)
#pragma unroll
            for (int b = 0; b < 4; ++b) M[a][b] = 0.0f;

        const uint32_t bb = smb + (p & 1) * BUFSZ;
        const uint32_t aA = bb + aAo;
        const uint32_t aB = bb + aBo;

#pragma unroll
        for (int ks = 0; ks < NKS; ++ks) {
            uint32_t a[4], b[4][2];
            LDSM_X4(a[0], a[1], a[2], a[3], aA + ks * 32);
            LDSM_X4(b[0][0], b[1][0], b[0][1], b[1][1], aB + ks * 32);
            LDSM_X4(b[2][0], b[3][0], b[2][1], b[3][1], aB + 16 * ST + ks * 32);
#pragma unroll
            for (int nt = 0; nt < 4; ++nt)
                asm volatile(
                    "mma.sync.aligned.m16n8k16.row.col.f32.f16.f16.f32 "
                    "{%0,%1,%2,%3}, {%4,%5,%6,%7}, {%8,%9}, {%0,%1,%2,%3};"
                    : "+f"(M[nt][0]), "+f"(M[nt][1]),
                      "+f"(M[nt][2]), "+f"(M[nt][3])
                    : "r"(a[0]), "r"(a[1]), "r"(a[2]), "r"(a[3]),
                      "r"(b[nt][0]), "r"(b[nt][1]));
        }
        __syncthreads();

        // inverse-transform fold: At = [[1,1,1,0],[0,1,-1,-1]]
        int pi = p >> 2, pj = p & 3;
        float fi0 = (pi < 3) ? 1.0f : 0.0f;
        float fi1 = (pi == 0) ? 0.0f : ((pi == 1) ? 1.0f : -1.0f);
        float fj0 = (pj < 3) ? 1.0f : 0.0f;
        float fj1 = (pj == 0) ? 0.0f : ((pj == 1) ? 1.0f : -1.0f);
        float c00 = fi0 * fj0, c01 = fi0 * fj1, c10 = fi1 * fj0, c11 = fi1 * fj1;
#pragma unroll
        for (int nt = 0; nt < 4; ++nt)
#pragma unroll
            for (int e = 0; e < 4; ++e) {
                float m = M[nt][e];
                Z[nt][e][0] += c00 * m;
                Z[nt][e][1] += c01 * m;
                Z[nt][e][2] += c10 * m;
                Z[nt][e][3] += c11 * m;
            }
    }

    // Epilogue: Z -> out NCHW fp32.
    const int g = lane >> 2, t4 = lane & 3;
    const int oc0 = octile * 64 + wm * 16 + g;
#pragma unroll
    for (int nt = 0; nt < 4; ++nt) {
        int tl0 = n0 + wn * 32 + nt * 8 + 2 * t4;
#pragma unroll
        for (int et = 0; et < 2; ++et) {
            int tile = tl0 + et;
            int img = tile / 784, rem = tile % 784;
            int tr = rem / 28, tc = rem % 28;
            size_t obase = ((size_t)img * CTOT + oc0) * HWX + (2 * tr) * WW + 2 * tc;
#pragma unroll
            for (int er = 0; er < 2; ++er) {
                int e = er * 2 + et;
                size_t ob = obase + (size_t)er * 8 * HWX;
                *(float2*)(out + ob)      = make_float2(Z[nt][e][0], Z[nt][e][1]);
                *(float2*)(out + ob + WW) = make_float2(Z[nt][e][2], Z[nt][e][3]);
            }
        }
    }
}

__global__ __launch_bounds__(256, 2) void wino_gemm_kernel(float* __restrict__ out)
{
    extern __shared__ __half smh[];
    if (blockIdx.x == 0) wino_body<true>(out, smh);
    else                 wino_body<false>(out, smh);
}

// ---------------------------------------------------------------------------
// Inputs: x, w11, w13, w15, w17, w21, w23, w25, w27, w2d1, w2d2, n_segment
// ---------------------------------------------------------------------------
extern "C" void kernel_launch(void* const* d_in, const int* in_sizes, int n_in,
                              void* d_out, int out_size)
{
    const float* x    = (const float*)d_in[0];
    const float* w11  = (const float*)d_in[1];
    const float* w13  = (const float*)d_in[2];
    const float* w15  = (const float*)d_in[3];
    const float* w17  = (const float*)d_in[4];
    const float* w21  = (const float*)d_in[5];
    const float* w23  = (const float*)d_in[6];
    const float* w25  = (const float*)d_in[7];
    const float* w27  = (const float*)d_in[8];
    const float* w2d1 = (const float*)d_in[9];
    const float* w2d2 = (const float*)d_in[10];
    float* out = (float*)d_out;

    cudaFuncSetAttribute(wino_gemm_kernel,
                         cudaFuncAttributeMaxDynamicSharedMemorySize, SMEM_BYTES);

    dim3 g1(98, 8, 8), b1(32, 8);
    temporal_nhwc_kernel<<<g1, b1>>>(x, w11, w13, w15, w17, w21, w23, w25, w27);
    wino_u_kernel<<<160, 256>>>(w2d1, w2d2);
    wino_v_kernel<<<NTILE / 2, 256>>>();
    wino_gemm_kernel<<<dim3(4, 784), 256, SMEM_BYTES>>>(out);
}

// round 13
// speedup vs baseline: 1.2603x; 1.2603x over previous
#include <cuda_runtime.h>
#include <cuda_fp16.h>
#include <cstdint>

#define HWX   3136
#define WW    56
#define CTOT  256
#define NIMG  64
#define NPIX  (NIMG * HWX)          // 200704
#define NTILE 50176                 // 64 img * 28*28 winograd tiles

// Intermediate y, NHWC fp32: [img*hw][256]
__device__ float g_y[(size_t)NPIX * CTOT];
// Winograd-transformed input V[pos 16][tile][ic 256], fp16
__device__ __half g_V[(size_t)16 * NTILE * 256];
// Winograd-transformed weights, fp16
__device__ __half g_UA[16 * 64 * 64];      // [p][oc][ic]
__device__ __half g_UB[16 * 192 * 192];    // [p][oc][ic]

__device__ __forceinline__ uint32_t smem_u32(const void* p) {
    uint32_t a;
    asm("{ .reg .u64 t; cvta.to.shared.u64 t, %1; cvt.u32.u64 %0, t; }" : "=r"(a) : "l"(p));
    return a;
}

// ---------------------------------------------------------------------------
// Stage 1: temporal DW conv, NCHW fp32 -> NHWC fp32, smem transpose.
// ---------------------------------------------------------------------------
__global__ __launch_bounds__(256) void temporal_nhwc_kernel(
    const float* __restrict__ x,
    const float* __restrict__ w11, const float* __restrict__ w13,
    const float* __restrict__ w15, const float* __restrict__ w17,
    const float* __restrict__ w21, const float* __restrict__ w23,
    const float* __restrict__ w25, const float* __restrict__ w27)
{
    __shared__ float s[32][33];
    const int tx = threadIdx.x, ty = threadIdx.y;
    const int n = blockIdx.z, c0 = blockIdx.y * 32, hw0 = blockIdx.x * 32;

    float v[4][8], o[4][8];
#pragma unroll
    for (int j = 0; j < 4; j++) {
        int c = c0 + ty * 4 + j;
        const float* xb = x + ((size_t)(n * 8) * CTOT + c) * HWX + hw0 + tx;
#pragma unroll
        for (int t = 0; t < 8; t++) v[j][t] = xb[(size_t)t * CTOT * HWX];
    }
#pragma unroll
    for (int j = 0; j < 4; j++) {
        int c = c0 + ty * 4 + j;
        int k, cg; const float* wp;
        if      (c < 16)  { k = 1; wp = w11; cg = c;       }
        else if (c < 32)  { k = 3; wp = w13; cg = c - 16;  }
        else if (c < 48)  { k = 5; wp = w15; cg = c - 32;  }
        else if (c < 64)  { k = 7; wp = w17; cg = c - 48;  }
        else if (c < 112) { k = 1; wp = w21; cg = c - 64;  }
        else if (c < 160) { k = 3; wp = w23; cg = c - 112; }
        else if (c < 208) { k = 5; wp = w25; cg = c - 160; }
        else              { k = 7; wp = w27; cg = c - 208; }
        float wr[7];
#pragma unroll
        for (int q = 0; q < 7; q++) wr[q] = (q < k) ? __ldg(&wp[cg * k + q]) : 0.0f;
        int pad = (k - 1) >> 1;
#pragma unroll
        for (int t = 0; t < 8; t++) {
            float sum = 0.0f;
#pragma unroll
            for (int q = 0; q < 7; q++) {
                int tt = t + q - pad;
                if (q < k && tt >= 0 && tt < 8) sum += wr[q] * v[j][tt];
            }
            o[j][t] = sum;
        }
    }
#pragma unroll
    for (int t = 0; t < 8; t++) {
#pragma unroll
        for (int j = 0; j < 4; j++) s[tx][ty * 4 + j] = o[j][t];
        __syncthreads();
        float* yb = g_y + ((size_t)(n * 8 + t) * HWX + hw0) * CTOT + c0;
#pragma unroll
        for (int j = 0; j < 4; j++)
            yb[(size_t)(ty * 4 + j) * CTOT + tx] = s[ty * 4 + j][tx];
        __syncthreads();
    }
}

// ---------------------------------------------------------------------------
// Winograd input transform: g_y (NHWC fp32) -> V[p][tile][ic] fp16.
// ---------------------------------------------------------------------------
__global__ __launch_bounds__(256) void wino_v_kernel()
{
    const int tid  = threadIdx.x;
    const int tile = blockIdx.x * 2 + (tid >> 7);
    const int icp  = tid & 127;
    const int img  = tile / 784, rem = tile % 784;
    const int tr = rem / 28, tc = rem % 28;
    const int h0 = 2 * tr - 1, w0 = 2 * tc - 1;
    const float* yb = g_y + (size_t)img * HWX * CTOT + icp * 2;

    float ex[4][4], ey[4][4];
#pragma unroll
    for (int c = 0; c < 4; ++c) {
        float dx[4], dy[4];
#pragma unroll
        for (int r = 0; r < 4; ++r) {
            int h = h0 + r, w = w0 + c;
            float2 v = make_float2(0.0f, 0.0f);
            if ((unsigned)h < 56u && (unsigned)w < 56u)
                v = *(const float2*)(yb + (size_t)(h * WW + w) * CTOT);
            dx[r] = v.x; dy[r] = v.y;
        }
        ex[0][c] = dx[0] - dx[2];  ey[0][c] = dy[0] - dy[2];
        ex[1][c] = dx[1] + dx[2];  ey[1][c] = dy[1] + dy[2];
        ex[2][c] = dx[2] - dx[1];  ey[2][c] = dy[2] - dy[1];
        ex[3][c] = dx[1] - dx[3];  ey[3][c] = dy[1] - dy[3];
    }
#pragma unroll
    for (int i = 0; i < 4; ++i) {
        float vx[4], vy[4];
        vx[0] = ex[i][0] - ex[i][2];  vy[0] = ey[i][0] - ey[i][2];
        vx[1] = ex[i][1] + ex[i][2];  vy[1] = ey[i][1] + ey[i][2];
        vx[2] = ex[i][2] - ex[i][1];  vy[2] = ey[i][2] - ey[i][1];
        vx[3] = ex[i][1] - ex[i][3];  vy[3] = ey[i][1] - ey[i][3];
#pragma unroll
        for (int j = 0; j < 4; ++j) {
            *(__half2*)(g_V + ((size_t)(i * 4 + j) * NTILE + tile) * 256 + icp * 2)
                = __floats2half2_rn(vx[j], vy[j]);
        }
    }
}

// ---------------------------------------------------------------------------
// Winograd weight transform: U = G g G^T.
// ---------------------------------------------------------------------------
__global__ void wino_u_kernel(const float* __restrict__ w2d1,
                              const float* __restrict__ w2d2)
{
    int i = blockIdx.x * 256 + threadIdx.x;
    if (i >= 4096 + 36864) return;
    const float* src;
    __half* dst0; int rstride, rowoff;
    if (i < 4096) {
        int oc = i >> 6, ic = i & 63;
        src = w2d1 + (oc * 64 + ic) * 9;
        dst0 = g_UA; rstride = 64 * 64; rowoff = oc * 64 + ic;
    } else {
        int j = i - 4096;
        int oc = j / 192, ic = j % 192;
        src = w2d2 + (oc * 192 + ic) * 9;
        dst0 = g_UB; rstride = 192 * 192; rowoff = oc * 192 + ic;
    }
    float g[3][3];
#pragma unroll
    for (int a = 0; a < 3; ++a)
#pragma unroll
        for (int b = 0; b < 3; ++b) g[a][b] = src[a * 3 + b];
    float u[4][3];
#pragma unroll
    for (int b = 0; b < 3; ++b) {
        u[0][b] = g[0][b];
        u[1][b] = 0.5f * (g[0][b] + g[1][b] + g[2][b]);
        u[2][b] = 0.5f * (g[0][b] - g[1][b] + g[2][b]);
        u[3][b] = g[2][b];
    }
#pragma unroll
    for (int r = 0; r < 4; ++r) {
        float U0 = u[r][0];
        float U1 = 0.5f * (u[r][0] + u[r][1] + u[r][2]);
        float U2 = 0.5f * (u[r][0] - u[r][1] + u[r][2]);
        float U3 = u[r][2];
        dst0[(r * 4 + 0) * rstride + rowoff] = __float2half_rn(U0);
        dst0[(r * 4 + 1) * rstride + rowoff] = __float2half_rn(U1);
        dst0[(r * 4 + 2) * rstride + rowoff] = __float2half_rn(U2);
        dst0[(r * 4 + 3) * rstride + rowoff] = __float2half_rn(U3);
    }
}

// ---------------------------------------------------------------------------
// Winograd GEMM v4: 3 CTAs/SM. CTA = 64 oc x 32 tiles, 8 warps of 16x16.
// Group B: K split into 2 chunks of 96 per position. 3 buffers, 1 sync/chunk.
// Coalesced staging (consecutive threads -> consecutive 16B), constexpr divs.
// ---------------------------------------------------------------------------
#define SMEM_BYTES 59904u        // 3 x 96 rows x 208 B (group-B case)

#define LDSM_X4(r0, r1, r2, r3, addr) \
    asm volatile("ldmatrix.sync.aligned.m8n8.x4.shared.b16 {%0,%1,%2,%3}, [%4];" \
        : "=r"(r0), "=r"(r1), "=r"(r2), "=r"(r3) : "r"(addr))

template<bool ISA>
__device__ __forceinline__ void wino_body(float* __restrict__ out,
                                          const __half* __restrict__ smbase)
{
    constexpr int ICN   = ISA ? 64 : 192;
    constexpr int KH    = ISA ? 64 : 96;      // K per chunk
    constexpr int NCHP  = ISA ? 1 : 2;        // chunks per position
    constexpr int NCH   = 16 * NCHP;          // total chunks
    constexpr int NKS   = KH / 16;            // 4 / 6 ks steps per chunk
    constexpr int CPR   = KH / 8;             // 16B chunks per row: 8 / 12
    constexpr uint32_t ST    = (uint32_t)(KH * 2 + 16);   // 144 / 208
    constexpr uint32_t BOFF  = 64u * ST;
    constexpr uint32_t BUFSZ = 96u * ST;
    constexpr int CH_A = 64 * CPR;            // 512 / 768  (multiples of 256)
    constexpr int CH_B = 32 * CPR;            // 256 / 384
    constexpr size_t APS = (size_t)ICN * (ISA ? 64 : 192);
    constexpr size_t BPS = (size_t)NTILE * 256;

    const uint32_t smb = smem_u32(smbase);
    const int tid = threadIdx.x, wid = tid >> 5, lane = tid & 31;
    const int octile = blockIdx.x;
    const int n0 = blockIdx.y * 32;

    const __half* Ab = ISA ? g_UA : g_UB + (size_t)((octile - 1) * 64) * 192;
    const __half* Bb = g_V + (size_t)n0 * 256 + (ISA ? 0 : 64);

    auto stage = [&](int c, int buf) {
        const int p = c / NCHP, q = c - (c / NCHP) * NCHP;   // constexpr divisor
        const __half* As = Ab + (size_t)p * APS + q * KH;
        const __half* Bs = Bb + (size_t)p * BPS + q * KH;
        const uint32_t bb = smb + buf * BUFSZ;
#pragma unroll
        for (int j = 0; j < CH_A / 256; ++j) {
            int i = tid + j * 256;
            int row = i / CPR, kq = i - row * CPR;
            asm volatile("cp.async.cg.shared.global [%0], [%1], 16;"
                :: "r"(bb + row * ST + kq * 16), "l"(As + (size_t)row * ICN + kq * 8));
        }
#pragma unroll
        for (int j = 0; j < (CH_B + 255) / 256; ++j) {
            int i = tid + j * 256;
            if (i < CH_B) {
                int row = i / CPR, kq = i - row * CPR;
                asm volatile("cp.async.cg.shared.global [%0], [%1], 16;"
                    :: "r"(bb + BOFF + row * ST + kq * 16), "l"(Bs + (size_t)row * 256 + kq * 8));
            }
        }
        asm volatile("cp.async.commit_group;" ::: "memory");
    };

    float Z[2][4][4];
#pragma unroll
    for (int a = 0; a < 2; ++a)
#pragma unroll
        for (int b = 0; b < 4; ++b)
#pragma unroll
            for (int c = 0; c < 4; ++c) Z[a][b][c] = 0.0f;

    float M[2][4];
    const int wm = wid & 3, wn = wid >> 2;
    const int l15 = lane & 15;
    const int kh16 = (lane >> 4) * 16;
    const uint32_t aAo = (wm * 16 + l15) * ST + kh16;
    const uint32_t aBo = BOFF + (wn * 16 + l15) * ST + kh16;

    stage(0, 0);
    stage(1, 1);

    for (int c = 0; c < NCH; ++c) {
        if (c + 1 < NCH)
            asm volatile("cp.async.wait_group 1;" ::: "memory");
        else
            asm volatile("cp.async.wait_group 0;" ::: "memory");
        __syncthreads();
        if (c + 2 < NCH) stage(c + 2, (c + 2) % 3);

        const int q = c - (c / NCHP) * NCHP;
        if (q == 0) {
#pragma unroll
            for (int a = 0; a < 2; ++a)
#pragma unroll
                for (int b = 0; b < 4; ++b) M[a][b] = 0.0f;
        }

        const uint32_t bb = smb + (c % 3) * BUFSZ;
        const uint32_t aA = bb + aAo;
        const uint32_t aB = bb + aBo;

#pragma unroll
        for (int ks = 0; ks < NKS; ++ks) {
            uint32_t a[4], b[2][2];
            LDSM_X4(a[0], a[1], a[2], a[3], aA + ks * 32);
            LDSM_X4(b[0][0], b[1][0], b[0][1], b[1][1], aB + ks * 32);
#pragma unroll
            for (int nt = 0; nt < 2; ++nt)
                asm volatile(
                    "mma.sync.aligned.m16n8k16.row.col.f32.f16.f16.f32 "
                    "{%0,%1,%2,%3}, {%4,%5,%6,%7}, {%8,%9}, {%0,%1,%2,%3};"
                    : "+f"(M[nt][0]), "+f"(M[nt][1]),
                      "+f"(M[nt][2]), "+f"(M[nt][3])
                    : "r"(a[0]), "r"(a[1]), "r"(a[2]), "r"(a[3]),
                      "r"(b[nt][0]), "r"(b[nt][1]));
        }

        if (q == NCHP - 1) {
            // inverse-transform fold: At = [[1,1,1,0],[0,1,-1,-1]]
            const int p = c / NCHP;
            int pi = p >> 2, pj = p & 3;
            float fi0 = (pi < 3) ? 1.0f : 0.0f;
            float fi1 = (pi == 0) ? 0.0f : ((pi == 1) ? 1.0f : -1.0f);
            float fj0 = (pj < 3) ? 1.0f : 0.0f;
            float fj1 = (pj == 0) ? 0.0f : ((pj == 1) ? 1.0f : -1.0f);
            float c00 = fi0 * fj0, c01 = fi0 * fj1, c10 = fi1 * fj0, c11 = fi1 * fj1;
#pragma unroll
            for (int nt = 0; nt < 2; ++nt)
#pragma unroll
                for (int e = 0; e < 4; ++e) {
                    float m = M[nt][e];
                    Z[nt][e][0] += c00 * m;
                    Z[nt][e][1] += c01 * m;
                    Z[nt][e][2] += c10 * m;
                    Z[nt][e][3] += c11 * m;
                }
        }
    }

    // Epilogue: Z -> out NCHW fp32.
    const int g = lane >> 2, t4 = lane & 3;
    const int oc0 = octile * 64 + wm * 16 + g;
#pragma unroll
    for (int nt = 0; nt < 2; ++nt) {
        int tl0 = n0 + wn * 16 + nt * 8 + 2 * t4;
#pragma unroll
        for (int et = 0; et < 2; ++et) {
            int tile = tl0 + et;
            int img = tile / 784, rem = tile % 784;
            int tr = rem / 28, tc = rem % 28;
            size_t obase = ((size_t)img * CTOT + oc0) * HWX + (2 * tr) * WW + 2 * tc;
#pragma unroll
            for (int er = 0; er < 2; ++er) {
                int e = er * 2 + et;
                size_t ob = obase + (size_t)er * 8 * HWX;
                *(float2*)(out + ob)      = make_float2(Z[nt][e][0], Z[nt][e][1]);
                *(float2*)(out + ob + WW) = make_float2(Z[nt][e][2], Z[nt][e][3]);
            }
        }
    }
}

__global__ __launch_bounds__(256, 3) void wino_gemm_kernel(float* __restrict__ out)
{
    extern __shared__ __half smh[];
    if (blockIdx.x == 0) wino_body<true>(out, smh);
    else                 wino_body<false>(out, smh);
}

// ---------------------------------------------------------------------------
// Inputs: x, w11, w13, w15, w17, w21, w23, w25, w27, w2d1, w2d2, n_segment
// ---------------------------------------------------------------------------
extern "C" void kernel_launch(void* const* d_in, const int* in_sizes, int n_in,
                              void* d_out, int out_size)
{
    const float* x    = (const float*)d_in[0];
    const float* w11  = (const float*)d_in[1];
    const float* w13  = (const float*)d_in[2];
    const float* w15  = (const float*)d_in[3];
    const float* w17  = (const float*)d_in[4];
    const float* w21  = (const float*)d_in[5];
    const float* w23  = (const float*)d_in[6];
    const float* w25  = (const float*)d_in[7];
    const float* w27  = (const float*)d_in[8];
    const float* w2d1 = (const float*)d_in[9];
    const float* w2d2 = (const float*)d_in[10];
    float* out = (float*)d_out;

    cudaFuncSetAttribute(wino_gemm_kernel,
                         cudaFuncAttributeMaxDynamicSharedMemorySize, SMEM_BYTES);

    dim3 g1(98, 8, 8), b1(32, 8);
    temporal_nhwc_kernel<<<g1, b1>>>(x, w11, w13, w15, w17, w21, w23, w25, w27);
    wino_u_kernel<<<160, 256>>>(w2d1, w2d2);
    wino_v_kernel<<<NTILE / 2, 256>>>();
    wino_gemm_kernel<<<dim3(4, 1568), 256, SMEM_BYTES>>>(out);
}